// round 7
// baseline (speedup 1.0000x reference)
#include <cuda_runtime.h>
#include <cuda_fp16.h>
#include <math.h>

#define N_NODES 50000
#define FIN 128
#define H1 8
#define F1 128
#define E_MAX 800000
#define ET_MAX (E_MAX + N_NODES)
#define NEG_SLOPE 0.2f
#define SCAN_NB ((N_NODES + 1023) / 1024)   // 49

// ------------------------- scratch -------------------------
__device__ __half g_h1h[N_NODES * F1];     // fp16 x @ W1 (node1 gathers)
__device__ float g_asrc[N_NODES * H1];
__device__ float g_adst[N_NODES * H1];
__device__ float g_h2[N_NODES * 2];
__device__ float g_a2s[N_NODES];
__device__ float g_a2d[N_NODES];
__device__ int   g_src[ET_MAX];
__device__ int   g_dst[ET_MAX];
__device__ int   g_csr_src[ET_MAX];
__device__ int   g_start[N_NODES + 1];
__device__ int   g_deg[N_NODES];
__device__ int   g_cnt[N_NODES];
__device__ int   g_bsum[SCAN_NB];
__device__ int   g_boff[SCAN_NB];
__device__ int   g_is64;

__device__ __forceinline__ float leaky(float v) { return v > 0.f ? v : NEG_SLOPE * v; }

// ------------------------- dtype probe -------------------------
__global__ void probe_kernel(const void* ei) {
    const long long* p = (const long long*)ei;
    int bad = 0;
    for (int i = threadIdx.x; i < 2048; i += 256) {
        long long v = p[i];
        if (v < 0 || v >= (long long)N_NODES) bad = 1;
    }
    bad = __syncthreads_or(bad);
    if (threadIdx.x == 0) g_is64 = bad ? 0 : 1;
}

__global__ void zero_kernel() {
    int i = blockIdx.x * blockDim.x + threadIdx.x;
    if (i < N_NODES) { g_deg[i] = 0; g_cnt[i] = 0; }
}

__global__ void convert_kernel(const void* ei, int E, int ET) {
    int i = blockIdx.x * blockDim.x + threadIdx.x;
    if (i >= ET) return;
    int s, d;
    if (i < E) {
        if (g_is64) {
            const long long* p = (const long long*)ei;
            s = (int)p[i]; d = (int)p[E + i];
        } else {
            const int* p = (const int*)ei;
            s = p[i]; d = p[E + i];
        }
    } else {
        s = d = i - E;
    }
    g_src[i] = s;
    g_dst[i] = d;
    atomicAdd(&g_deg[d], 1);
}

// ------------------------- multi-block scan -------------------------
__global__ void scanA_kernel() {
    int i = blockIdx.x * 1024 + threadIdx.x;
    int v = (i < N_NODES) ? g_deg[i] : 0;
    int lane = threadIdx.x & 31, wid = threadIdx.x >> 5;
    int x = v;
#pragma unroll
    for (int o = 1; o < 32; o <<= 1) {
        int t = __shfl_up_sync(0xffffffffu, x, o);
        if (lane >= o) x += t;
    }
    __shared__ int wsum[32];
    if (lane == 31) wsum[wid] = x;
    __syncthreads();
    if (wid == 0) {
        int y = wsum[lane];
#pragma unroll
        for (int o = 1; o < 32; o <<= 1) {
            int t = __shfl_up_sync(0xffffffffu, y, o);
            if (lane >= o) y += t;
        }
        wsum[lane] = y;
    }
    __syncthreads();
    int incl = x + (wid > 0 ? wsum[wid - 1] : 0);
    if (i < N_NODES) g_start[i] = incl - v;
    if (threadIdx.x == 1023) g_bsum[blockIdx.x] = incl;
}

__global__ void scanB_kernel() {
    int lane = threadIdx.x;
    int i0 = 2 * lane, i1 = 2 * lane + 1;
    int a = (i0 < SCAN_NB) ? g_bsum[i0] : 0;
    int b = (i1 < SCAN_NB) ? g_bsum[i1] : 0;
    int loc = a + b;
    int x = loc;
#pragma unroll
    for (int o = 1; o < 32; o <<= 1) {
        int t = __shfl_up_sync(0xffffffffu, x, o);
        if (lane >= o) x += t;
    }
    int excl = x - loc;
    if (i0 < SCAN_NB) g_boff[i0] = excl;
    if (i1 < SCAN_NB) g_boff[i1] = excl + a;
    if (lane == 31) g_start[N_NODES] = x;
}

__global__ void scanC_kernel() {
    int i = blockIdx.x * blockDim.x + threadIdx.x;
    if (i < N_NODES) g_start[i] += g_boff[i >> 10];
}

__global__ void scatter_kernel(int ET) {
    int i = blockIdx.x * blockDim.x + threadIdx.x;
    if (i >= ET) return;
    int d = g_dst[i];
    int pos = g_start[d] + atomicAdd(&g_cnt[d], 1);
    g_csr_src[pos] = g_src[i];
}

// ------------------------- GEMM: h1 = x @ W1 (prefetched, fused attdot, fp16 store) -------------------------
#define BM 128
#define BK 8
__global__ void __launch_bounds__(256, 2)
gemm1_kernel(const float* __restrict__ X, const float* __restrict__ W,
             const float* __restrict__ att_s, const float* __restrict__ att_d, int M) {
    __shared__ __align__(16) float As[BK][BM];
    __shared__ __align__(16) float Bs[BK][F1];
    __shared__ float s_as[F1], s_ad[F1];
    int tid = threadIdx.x;
    int tx = tid & 15;
    int ty = tid >> 4;
    int rowBase = blockIdx.x * BM;

    if (tid < F1) { s_as[tid] = att_s[tid]; s_ad[tid] = att_d[tid]; }

    int lrow = tid >> 1;
    int lhalf = tid & 1;
    int grow = rowBase + lrow;
    const float* Xrow = X + (size_t)grow * FIN;
    int wrow = tid >> 5;
    int wcol = (tid & 31) * 4;

    float acc[8][8];
#pragma unroll
    for (int i = 0; i < 8; i++)
#pragma unroll
        for (int j = 0; j < 8; j++) acc[i][j] = 0.f;

    // prefetch first tile
    float4 xv = make_float4(0.f, 0.f, 0.f, 0.f);
    if (grow < M) xv = *(const float4*)(Xrow + lhalf * 4);
    float4 wv = *(const float4*)&W[(size_t)wrow * F1 + wcol];

    for (int k0 = 0; k0 < FIN; k0 += BK) {
        As[lhalf * 4 + 0][lrow] = xv.x;
        As[lhalf * 4 + 1][lrow] = xv.y;
        As[lhalf * 4 + 2][lrow] = xv.z;
        As[lhalf * 4 + 3][lrow] = xv.w;
        *(float4*)&Bs[wrow][wcol] = wv;
        __syncthreads();
        // prefetch next tile while computing
        if (k0 + BK < FIN) {
            xv = make_float4(0.f, 0.f, 0.f, 0.f);
            if (grow < M) xv = *(const float4*)(Xrow + k0 + BK + lhalf * 4);
            wv = *(const float4*)&W[(size_t)(k0 + BK + wrow) * F1 + wcol];
        }
#pragma unroll
        for (int kk = 0; kk < BK; kk++) {
            float4 a0 = *(const float4*)&As[kk][ty * 8];
            float4 a1 = *(const float4*)&As[kk][ty * 8 + 4];
            float4 b0 = *(const float4*)&Bs[kk][tx * 8];
            float4 b1 = *(const float4*)&Bs[kk][tx * 8 + 4];
            float av[8] = {a0.x, a0.y, a0.z, a0.w, a1.x, a1.y, a1.z, a1.w};
            float bv[8] = {b0.x, b0.y, b0.z, b0.w, b1.x, b1.y, b1.z, b1.w};
#pragma unroll
            for (int i = 0; i < 8; i++)
#pragma unroll
                for (int j = 0; j < 8; j++) acc[i][j] += av[i] * bv[j];
        }
        __syncthreads();
    }

    int head = tx >> 1;
    int cbase = head * 16 + (tx & 1) * 8;
#pragma unroll
    for (int i = 0; i < 8; i++) {
        int gr = rowBase + ty * 8 + i;
        if (gr < M) {
            __half2 h0 = __floats2half2_rn(acc[i][0], acc[i][1]);
            __half2 h1v = __floats2half2_rn(acc[i][2], acc[i][3]);
            __half2 h2v = __floats2half2_rn(acc[i][4], acc[i][5]);
            __half2 h3 = __floats2half2_rn(acc[i][6], acc[i][7]);
            uint4 pk;
            pk.x = *(unsigned*)&h0; pk.y = *(unsigned*)&h1v;
            pk.z = *(unsigned*)&h2v; pk.w = *(unsigned*)&h3;
            *(uint4*)&g_h1h[(size_t)gr * F1 + tx * 8] = pk;
        }
        float ps = 0.f, pd = 0.f;
#pragma unroll
        for (int j = 0; j < 8; j++) {
            ps += acc[i][j] * s_as[cbase + j];
            pd += acc[i][j] * s_ad[cbase + j];
        }
        ps += __shfl_xor_sync(0xffffffffu, ps, 1);
        pd += __shfl_xor_sync(0xffffffffu, pd, 1);
        if ((tx & 1) == 0 && gr < M) {
            g_asrc[gr * H1 + head] = ps;
            g_adst[gr * H1 + head] = pd;
        }
    }
}

// ------------------------- fused layer-1: two-phase per-chunk softmax-aggregate -------------------------
__device__ __forceinline__ void loadH4(int s, int lane, float* f) {
    uint2 u = *(const uint2*)&g_h1h[(size_t)s * F1 + lane * 4];
    float2 p0 = __half22float2(*(__half2*)&u.x);
    float2 p1 = __half22float2(*(__half2*)&u.y);
    f[0] = p0.x; f[1] = p0.y; f[2] = p1.x; f[3] = p1.y;
}

__global__ void __launch_bounds__(256)
node1_kernel(const float* __restrict__ b1, const float* __restrict__ W2,
             const float* __restrict__ as2, const float* __restrict__ ad2) {
    __shared__ float s_ee[8][32][8];   // [warpInBlock][edge][head] = 8KB
    int n = (blockIdx.x * blockDim.x + threadIdx.x) >> 5;
    if (n >= N_NODES) return;
    int wib = (threadIdx.x >> 5) & 7;
    int lane = threadIdx.x & 31;
    int rs = g_start[n], re = g_start[n + 1];
    int myh = lane >> 2;

    // adst for this node, all heads (broadcast load)
    float4 ad0 = *(const float4*)&g_adst[n * H1];
    float4 ad1 = *(const float4*)&g_adst[n * H1 + 4];

    float ssum = 0.f;
    float acc0 = 0.f, acc1 = 0.f, acc2 = 0.f, acc3 = 0.f;

    for (int c = rs; c < re; c += 32) {
        int cnt = re - c; if (cnt > 32) cnt = 32;
        // ---- phase A: lane-parallel ee computation for up to 32 edges ----
        int s = 0;
        if (lane < cnt) {
            s = g_csr_src[c + lane];
            float4 a0 = *(const float4*)&g_asrc[s * H1];
            float4 a1 = *(const float4*)&g_asrc[s * H1 + 4];
            float4 e0, e1;
            e0.x = __expf(leaky(a0.x + ad0.x));
            e0.y = __expf(leaky(a0.y + ad0.y));
            e0.z = __expf(leaky(a0.z + ad0.z));
            e0.w = __expf(leaky(a0.w + ad0.w));
            e1.x = __expf(leaky(a1.x + ad1.x));
            e1.y = __expf(leaky(a1.y + ad1.y));
            e1.z = __expf(leaky(a1.z + ad1.z));
            e1.w = __expf(leaky(a1.w + ad1.w));
            *(float4*)&s_ee[wib][lane][0] = e0;
            *(float4*)&s_ee[wib][lane][4] = e1;
        }
        __syncwarp();
        // ---- phase B: serial aggregation, deep-MLP h1 gathers ----
        int e = 0;
        for (; e + 7 < cnt; e += 8) {
            int si[8]; float eei[8]; float fv[8][4];
#pragma unroll
            for (int q = 0; q < 8; q++) {
                si[q] = __shfl_sync(0xffffffffu, s, e + q);
                eei[q] = s_ee[wib][e + q][myh];
            }
#pragma unroll
            for (int q = 0; q < 8; q++) loadH4(si[q], lane, fv[q]);
#pragma unroll
            for (int q = 0; q < 8; q++) {
                ssum += eei[q];
                acc0 += eei[q] * fv[q][0];
                acc1 += eei[q] * fv[q][1];
                acc2 += eei[q] * fv[q][2];
                acc3 += eei[q] * fv[q][3];
            }
        }
        for (; e < cnt; e++) {
            int se = __shfl_sync(0xffffffffu, s, e);
            float ee = s_ee[wib][e][myh];
            float f[4];
            loadH4(se, lane, f);
            ssum += ee;
            acc0 += ee * f[0]; acc1 += ee * f[1]; acc2 += ee * f[2]; acc3 += ee * f[3];
        }
        __syncwarp();
    }

    float inv = 1.f / ssum;
    // fused epilogue: v = elu(agg + b1), [p0,p1] = v @ W2, att2 dots
    float4 bv = *(const float4*)&b1[lane * 4];
    float v0 = acc0 * inv + bv.x;
    float v1 = acc1 * inv + bv.y;
    float v2 = acc2 * inv + bv.z;
    float v3 = acc3 * inv + bv.w;
    v0 = v0 > 0.f ? v0 : expm1f(v0);
    v1 = v1 > 0.f ? v1 : expm1f(v1);
    v2 = v2 > 0.f ? v2 : expm1f(v2);
    v3 = v3 > 0.f ? v3 : expm1f(v3);
    const float4* W4 = (const float4*)W2;
    float4 wa = W4[lane * 2];
    float4 wb = W4[lane * 2 + 1];
    float p0 = v0 * wa.x + v1 * wa.z + v2 * wb.x + v3 * wb.z;
    float p1 = v0 * wa.y + v1 * wa.w + v2 * wb.y + v3 * wb.w;
#pragma unroll
    for (int o = 16; o > 0; o >>= 1) {
        p0 += __shfl_xor_sync(0xffffffffu, p0, o);
        p1 += __shfl_xor_sync(0xffffffffu, p1, o);
    }
    if (lane == 0) {
        g_h2[n * 2]     = p0;
        g_h2[n * 2 + 1] = p1;
        g_a2s[n] = p0 * as2[0] + p1 * as2[1];
        g_a2d[n] = p0 * ad2[0] + p1 * ad2[1];
    }
}

// ------------------------- fused layer-2: single-pass softmax-aggregate -------------------------
__global__ void node2_kernel(float* __restrict__ out, const float* __restrict__ b2) {
    int n = (blockIdx.x * blockDim.x + threadIdx.x) >> 5;
    if (n >= N_NODES) return;
    int lane = threadIdx.x & 31;
    int rs = g_start[n], re = g_start[n + 1];
    float a2dn = g_a2d[n];

    float S = 0.f, n0 = 0.f, n1 = 0.f;
    for (int j = rs + lane; j < re; j += 32) {
        int s = g_csr_src[j];
        float ee = __expf(leaky(g_a2s[s] + a2dn));
        float2 h = *(const float2*)&g_h2[s * 2];
        S += ee; n0 += ee * h.x; n1 += ee * h.y;
    }
#pragma unroll
    for (int o = 16; o > 0; o >>= 1) {
        S  += __shfl_xor_sync(0xffffffffu, S, o);
        n0 += __shfl_xor_sync(0xffffffffu, n0, o);
        n1 += __shfl_xor_sync(0xffffffffu, n1, o);
    }
    if (lane == 0) {
        float inv = 1.f / S;
        out[n * 2]     = n0 * inv + b2[0];
        out[n * 2 + 1] = n1 * inv + b2[1];
    }
}

// ------------------------- launch -------------------------
extern "C" void kernel_launch(void* const* d_in, const int* in_sizes, int n_in,
                              void* d_out, int out_size) {
    const float* x   = (const float*)d_in[0];
    const void*  ei  = d_in[1];
    const float* W1  = (const float*)d_in[2];
    const float* as1 = (const float*)d_in[3];
    const float* ad1 = (const float*)d_in[4];
    const float* b1  = (const float*)d_in[5];
    const float* W2  = (const float*)d_in[6];
    const float* as2 = (const float*)d_in[7];
    const float* ad2 = (const float*)d_in[8];
    const float* b2  = (const float*)d_in[9];
    float* out = (float*)d_out;

    int E  = in_sizes[1] / 2;
    int ET = E + N_NODES;

    probe_kernel<<<1, 256>>>(ei);
    zero_kernel<<<(N_NODES + 255) / 256, 256>>>();
    convert_kernel<<<(ET + 255) / 256, 256>>>(ei, E, ET);
    scanA_kernel<<<SCAN_NB, 1024>>>();
    scanB_kernel<<<1, 32>>>();
    scanC_kernel<<<(N_NODES + 255) / 256, 256>>>();
    scatter_kernel<<<(ET + 255) / 256, 256>>>(ET);

    gemm1_kernel<<<(N_NODES + BM - 1) / BM, 256>>>(x, W1, as1, ad1, N_NODES);

    int nodeBlocks = (N_NODES * 32 + 255) / 256;
    node1_kernel<<<nodeBlocks, 256>>>(b1, W2, as2, ad2);
    node2_kernel<<<nodeBlocks, 256>>>(out, b2);
}

// round 8
// speedup vs baseline: 1.2776x; 1.2776x over previous
#include <cuda_runtime.h>
#include <cuda_fp16.h>
#include <math.h>

#define N_NODES 50000
#define FIN 128
#define H1 8
#define F1 128
#define E_MAX 800000
#define ET_MAX (E_MAX + N_NODES)
#define NEG_SLOPE 0.2f
#define SCAN_NB ((N_NODES + 1023) / 1024)   // 49

// ------------------------- scratch -------------------------
__device__ __half g_h1h[N_NODES * F1];     // fp16 x @ W1 (node1 gathers)
__device__ float g_asrc[N_NODES * H1];
__device__ float g_adst[N_NODES * H1];
__device__ float g_h2[N_NODES * 2];
__device__ float g_a2s[N_NODES];
__device__ float g_a2d[N_NODES];
__device__ int   g_src[ET_MAX];
__device__ int   g_dst[ET_MAX];
__device__ int   g_csr_src[ET_MAX];
__device__ int   g_start[N_NODES + 1];
__device__ int   g_deg[N_NODES];
__device__ int   g_cnt[N_NODES];
__device__ int   g_bsum[SCAN_NB];
__device__ int   g_boff[SCAN_NB];
__device__ int   g_is64;

__device__ __forceinline__ float leaky(float v) { return v > 0.f ? v : NEG_SLOPE * v; }

// ------------------------- dtype probe + counter zero (merged) -------------------------
__global__ void probe_zero_kernel(const void* ei) {
    int i = blockIdx.x * blockDim.x + threadIdx.x;
    if (i < N_NODES) { g_deg[i] = 0; g_cnt[i] = 0; }
    if (blockIdx.x == 0) {
        const long long* p = (const long long*)ei;
        int bad = 0;
        for (int k = threadIdx.x; k < 2048; k += 256) {
            long long v = p[k];
            if (v < 0 || v >= (long long)N_NODES) bad = 1;
        }
        bad = __syncthreads_or(bad);
        if (threadIdx.x == 0) g_is64 = bad ? 0 : 1;
    }
}

__global__ void convert_kernel(const void* ei, int E, int ET) {
    int i = blockIdx.x * blockDim.x + threadIdx.x;
    if (i >= ET) return;
    int s, d;
    if (i < E) {
        if (g_is64) {
            const long long* p = (const long long*)ei;
            s = (int)p[i]; d = (int)p[E + i];
        } else {
            const int* p = (const int*)ei;
            s = p[i]; d = p[E + i];
        }
    } else {
        s = d = i - E;
    }
    g_src[i] = s;
    g_dst[i] = d;
    atomicAdd(&g_deg[d], 1);
}

// ------------------------- multi-block scan -------------------------
__global__ void scanA_kernel() {
    int i = blockIdx.x * 1024 + threadIdx.x;
    int v = (i < N_NODES) ? g_deg[i] : 0;
    int lane = threadIdx.x & 31, wid = threadIdx.x >> 5;
    int x = v;
#pragma unroll
    for (int o = 1; o < 32; o <<= 1) {
        int t = __shfl_up_sync(0xffffffffu, x, o);
        if (lane >= o) x += t;
    }
    __shared__ int wsum[32];
    if (lane == 31) wsum[wid] = x;
    __syncthreads();
    if (wid == 0) {
        int y = wsum[lane];
#pragma unroll
        for (int o = 1; o < 32; o <<= 1) {
            int t = __shfl_up_sync(0xffffffffu, y, o);
            if (lane >= o) y += t;
        }
        wsum[lane] = y;
    }
    __syncthreads();
    int incl = x + (wid > 0 ? wsum[wid - 1] : 0);
    if (i < N_NODES) g_start[i] = incl - v;
    if (threadIdx.x == 1023) g_bsum[blockIdx.x] = incl;
}

__global__ void scanB_kernel() {
    int lane = threadIdx.x;
    int i0 = 2 * lane, i1 = 2 * lane + 1;
    int a = (i0 < SCAN_NB) ? g_bsum[i0] : 0;
    int b = (i1 < SCAN_NB) ? g_bsum[i1] : 0;
    int loc = a + b;
    int x = loc;
#pragma unroll
    for (int o = 1; o < 32; o <<= 1) {
        int t = __shfl_up_sync(0xffffffffu, x, o);
        if (lane >= o) x += t;
    }
    int excl = x - loc;
    if (i0 < SCAN_NB) g_boff[i0] = excl;
    if (i1 < SCAN_NB) g_boff[i1] = excl + a;
    if (lane == 31) g_start[N_NODES] = x;
}

__global__ void scanC_kernel() {
    int i = blockIdx.x * blockDim.x + threadIdx.x;
    if (i < N_NODES) g_start[i] += g_boff[i >> 10];
}

__global__ void scatter_kernel(int ET) {
    int i = blockIdx.x * blockDim.x + threadIdx.x;
    if (i >= ET) return;
    int d = g_dst[i];
    int pos = g_start[d] + atomicAdd(&g_cnt[d], 1);
    g_csr_src[pos] = g_src[i];
}

// ------------------------- GEMM: h1 = x @ W1 (prefetched, fused attdot, fp16 store) -------------------------
#define BM 128
#define BK 8
__global__ void __launch_bounds__(256, 2)
gemm1_kernel(const float* __restrict__ X, const float* __restrict__ W,
             const float* __restrict__ att_s, const float* __restrict__ att_d, int M) {
    __shared__ __align__(16) float As[BK][BM];
    __shared__ __align__(16) float Bs[BK][F1];
    __shared__ float s_as[F1], s_ad[F1];
    int tid = threadIdx.x;
    int tx = tid & 15;
    int ty = tid >> 4;
    int rowBase = blockIdx.x * BM;

    if (tid < F1) { s_as[tid] = att_s[tid]; s_ad[tid] = att_d[tid]; }

    int lrow = tid >> 1;
    int lhalf = tid & 1;
    int grow = rowBase + lrow;
    const float* Xrow = X + (size_t)grow * FIN;
    int wrow = tid >> 5;
    int wcol = (tid & 31) * 4;

    float acc[8][8];
#pragma unroll
    for (int i = 0; i < 8; i++)
#pragma unroll
        for (int j = 0; j < 8; j++) acc[i][j] = 0.f;

    float4 xv = make_float4(0.f, 0.f, 0.f, 0.f);
    if (grow < M) xv = *(const float4*)(Xrow + lhalf * 4);
    float4 wv = *(const float4*)&W[(size_t)wrow * F1 + wcol];

    for (int k0 = 0; k0 < FIN; k0 += BK) {
        As[lhalf * 4 + 0][lrow] = xv.x;
        As[lhalf * 4 + 1][lrow] = xv.y;
        As[lhalf * 4 + 2][lrow] = xv.z;
        As[lhalf * 4 + 3][lrow] = xv.w;
        *(float4*)&Bs[wrow][wcol] = wv;
        __syncthreads();
        if (k0 + BK < FIN) {
            xv = make_float4(0.f, 0.f, 0.f, 0.f);
            if (grow < M) xv = *(const float4*)(Xrow + k0 + BK + lhalf * 4);
            wv = *(const float4*)&W[(size_t)(k0 + BK + wrow) * F1 + wcol];
        }
#pragma unroll
        for (int kk = 0; kk < BK; kk++) {
            float4 a0 = *(const float4*)&As[kk][ty * 8];
            float4 a1 = *(const float4*)&As[kk][ty * 8 + 4];
            float4 b0 = *(const float4*)&Bs[kk][tx * 8];
            float4 b1 = *(const float4*)&Bs[kk][tx * 8 + 4];
            float av[8] = {a0.x, a0.y, a0.z, a0.w, a1.x, a1.y, a1.z, a1.w};
            float bv[8] = {b0.x, b0.y, b0.z, b0.w, b1.x, b1.y, b1.z, b1.w};
#pragma unroll
            for (int i = 0; i < 8; i++)
#pragma unroll
                for (int j = 0; j < 8; j++) acc[i][j] += av[i] * bv[j];
        }
        __syncthreads();
    }

    int head = tx >> 1;
    int cbase = head * 16 + (tx & 1) * 8;
#pragma unroll
    for (int i = 0; i < 8; i++) {
        int gr = rowBase + ty * 8 + i;
        if (gr < M) {
            __half2 h0 = __floats2half2_rn(acc[i][0], acc[i][1]);
            __half2 h1v = __floats2half2_rn(acc[i][2], acc[i][3]);
            __half2 h2v = __floats2half2_rn(acc[i][4], acc[i][5]);
            __half2 h3 = __floats2half2_rn(acc[i][6], acc[i][7]);
            uint4 pk;
            pk.x = *(unsigned*)&h0; pk.y = *(unsigned*)&h1v;
            pk.z = *(unsigned*)&h2v; pk.w = *(unsigned*)&h3;
            *(uint4*)&g_h1h[(size_t)gr * F1 + tx * 8] = pk;
        }
        float ps = 0.f, pd = 0.f;
#pragma unroll
        for (int j = 0; j < 8; j++) {
            ps += acc[i][j] * s_as[cbase + j];
            pd += acc[i][j] * s_ad[cbase + j];
        }
        ps += __shfl_xor_sync(0xffffffffu, ps, 1);
        pd += __shfl_xor_sync(0xffffffffu, pd, 1);
        if ((tx & 1) == 0 && gr < M) {
            g_asrc[gr * H1 + head] = ps;
            g_adst[gr * H1 + head] = pd;
        }
    }
}

// ------------------------- fused layer-1 (R6 form): single-pass softmax-aggregate + elu + W2 + att2 dots -------------------------
__device__ __forceinline__ void loadH4(int s, int lane, float* f) {
    uint2 u = *(const uint2*)&g_h1h[(size_t)s * F1 + lane * 4];
    float2 p0 = __half22float2(*(__half2*)&u.x);
    float2 p1 = __half22float2(*(__half2*)&u.y);
    f[0] = p0.x; f[1] = p0.y; f[2] = p1.x; f[3] = p1.y;
}

__global__ void node1_kernel(const float* __restrict__ b1, const float* __restrict__ W2,
                             const float* __restrict__ as2, const float* __restrict__ ad2) {
    int n = (blockIdx.x * blockDim.x + threadIdx.x) >> 5;
    if (n >= N_NODES) return;
    int lane = threadIdx.x & 31;
    int rs = g_start[n], re = g_start[n + 1];

    int myh = lane >> 2;
    float adm = g_adst[n * H1 + myh];
    float ssum = 0.f;
    float acc0 = 0.f, acc1 = 0.f, acc2 = 0.f, acc3 = 0.f;

    int j = rs;
    for (; j + 3 < re; j += 4) {
        int s0 = g_csr_src[j];
        int s1 = g_csr_src[j + 1];
        int s2 = g_csr_src[j + 2];
        int s3 = g_csr_src[j + 3];
        float av0 = __ldg(&g_asrc[s0 * H1 + myh]);
        float av1 = __ldg(&g_asrc[s1 * H1 + myh]);
        float av2 = __ldg(&g_asrc[s2 * H1 + myh]);
        float av3 = __ldg(&g_asrc[s3 * H1 + myh]);
        float f0[4], f1[4], f2[4], f3[4];
        loadH4(s0, lane, f0);
        loadH4(s1, lane, f1);
        loadH4(s2, lane, f2);
        loadH4(s3, lane, f3);
        float ee0 = __expf(leaky(av0 + adm));
        float ee1 = __expf(leaky(av1 + adm));
        float ee2 = __expf(leaky(av2 + adm));
        float ee3 = __expf(leaky(av3 + adm));
        ssum += (ee0 + ee1) + (ee2 + ee3);
        acc0 += ee0 * f0[0] + ee1 * f1[0] + ee2 * f2[0] + ee3 * f3[0];
        acc1 += ee0 * f0[1] + ee1 * f1[1] + ee2 * f2[1] + ee3 * f3[1];
        acc2 += ee0 * f0[2] + ee1 * f1[2] + ee2 * f2[2] + ee3 * f3[2];
        acc3 += ee0 * f0[3] + ee1 * f1[3] + ee2 * f2[3] + ee3 * f3[3];
    }
    for (; j < re; j++) {
        int s0 = g_csr_src[j];
        float av0 = __ldg(&g_asrc[s0 * H1 + myh]);
        float f0[4];
        loadH4(s0, lane, f0);
        float ee0 = __expf(leaky(av0 + adm));
        ssum += ee0;
        acc0 += ee0 * f0[0]; acc1 += ee0 * f0[1]; acc2 += ee0 * f0[2]; acc3 += ee0 * f0[3];
    }
    float inv = 1.f / ssum;

    float4 bv = *(const float4*)&b1[lane * 4];
    float v0 = acc0 * inv + bv.x;
    float v1 = acc1 * inv + bv.y;
    float v2 = acc2 * inv + bv.z;
    float v3 = acc3 * inv + bv.w;
    v0 = v0 > 0.f ? v0 : expm1f(v0);
    v1 = v1 > 0.f ? v1 : expm1f(v1);
    v2 = v2 > 0.f ? v2 : expm1f(v2);
    v3 = v3 > 0.f ? v3 : expm1f(v3);
    const float4* W4 = (const float4*)W2;
    float4 wa = W4[lane * 2];
    float4 wb = W4[lane * 2 + 1];
    float p0 = v0 * wa.x + v1 * wa.z + v2 * wb.x + v3 * wb.z;
    float p1 = v0 * wa.y + v1 * wa.w + v2 * wb.y + v3 * wb.w;
#pragma unroll
    for (int o = 16; o > 0; o >>= 1) {
        p0 += __shfl_xor_sync(0xffffffffu, p0, o);
        p1 += __shfl_xor_sync(0xffffffffu, p1, o);
    }
    if (lane == 0) {
        g_h2[n * 2]     = p0;
        g_h2[n * 2 + 1] = p1;
        g_a2s[n] = p0 * as2[0] + p1 * as2[1];
        g_a2d[n] = p0 * ad2[0] + p1 * ad2[1];
    }
}

// ------------------------- fused layer-2: single-pass softmax-aggregate -------------------------
__global__ void node2_kernel(float* __restrict__ out, const float* __restrict__ b2) {
    int n = (blockIdx.x * blockDim.x + threadIdx.x) >> 5;
    if (n >= N_NODES) return;
    int lane = threadIdx.x & 31;
    int rs = g_start[n], re = g_start[n + 1];
    float a2dn = g_a2d[n];

    float S = 0.f, n0 = 0.f, n1 = 0.f;
    for (int j = rs + lane; j < re; j += 32) {
        int s = g_csr_src[j];
        float ee = __expf(leaky(g_a2s[s] + a2dn));
        float2 h = *(const float2*)&g_h2[s * 2];
        S += ee; n0 += ee * h.x; n1 += ee * h.y;
    }
#pragma unroll
    for (int o = 16; o > 0; o >>= 1) {
        S  += __shfl_xor_sync(0xffffffffu, S, o);
        n0 += __shfl_xor_sync(0xffffffffu, n0, o);
        n1 += __shfl_xor_sync(0xffffffffu, n1, o);
    }
    if (lane == 0) {
        float inv = 1.f / S;
        out[n * 2]     = n0 * inv + b2[0];
        out[n * 2 + 1] = n1 * inv + b2[1];
    }
}

// ------------------------- launch (stream fork/join: gemm ∥ CSR build) -------------------------
extern "C" void kernel_launch(void* const* d_in, const int* in_sizes, int n_in,
                              void* d_out, int out_size) {
    const float* x   = (const float*)d_in[0];
    const void*  ei  = d_in[1];
    const float* W1  = (const float*)d_in[2];
    const float* as1 = (const float*)d_in[3];
    const float* ad1 = (const float*)d_in[4];
    const float* b1  = (const float*)d_in[5];
    const float* W2  = (const float*)d_in[6];
    const float* as2 = (const float*)d_in[7];
    const float* ad2 = (const float*)d_in[8];
    const float* b2  = (const float*)d_in[9];
    float* out = (float*)d_out;

    int E  = in_sizes[1] / 2;
    int ET = E + N_NODES;

    cudaStream_t sB;
    cudaEvent_t evFork, evJoin;
    cudaStreamCreateWithFlags(&sB, cudaStreamNonBlocking);
    cudaEventCreateWithFlags(&evFork, cudaEventDisableTiming);
    cudaEventCreateWithFlags(&evJoin, cudaEventDisableTiming);

    // fork gemm onto stream B (independent of CSR build)
    cudaEventRecord(evFork, 0);
    cudaStreamWaitEvent(sB, evFork, 0);
    gemm1_kernel<<<(N_NODES + BM - 1) / BM, 256, 0, sB>>>(x, W1, as1, ad1, N_NODES);
    cudaEventRecord(evJoin, sB);

    // CSR build on default stream
    probe_zero_kernel<<<(N_NODES + 255) / 256, 256>>>(ei);
    convert_kernel<<<(ET + 255) / 256, 256>>>(ei, E, ET);
    scanA_kernel<<<SCAN_NB, 1024>>>();
    scanB_kernel<<<1, 32>>>();
    scanC_kernel<<<(N_NODES + 255) / 256, 256>>>();
    scatter_kernel<<<(ET + 255) / 256, 256>>>(ET);

    // join: node pipeline needs both branches
    cudaStreamWaitEvent(0, evJoin, 0);

    int nodeBlocks = (N_NODES * 32 + 255) / 256;
    node1_kernel<<<nodeBlocks, 256>>>(b1, W2, as2, ad2);
    node2_kernel<<<nodeBlocks, 256>>>(out, b2);
}